// round 13
// baseline (speedup 1.0000x reference)
#include <cuda_runtime.h>
#include <cuda_fp16.h>
#include <cstdint>
#include <math.h>

static constexpr int S = 2048;
static constexpr int B = 32;
static constexpr int E = 1024;
static constexpr int A = 1024;
static constexpr int D = 1024;
static constexpr int R = S * B;

static constexpr int BN = 128;
static constexpr int BKC = 64;              // k per chunk
static constexpr int CHUNKS = E / BKC;      // 16
static constexpr int NPASS = A / BN;        // 8
static constexpr int GTOT = NPASS * CHUNKS; // 128 global chunks
static constexpr int SCH = 16;
static constexpr int NTHR = 512;

// mixed tiling: 192 big CTAs (256 rows) + 128 small CTAs (128 rows)
static constexpr int NBIG = 192;
static constexpr int BIGROWS = NBIG * 256;  // 49152
static constexpr int GRID_E = NBIG + (R - BIGROWS) / 128;  // 320

// smem: 3 stages x (32KB A + 16KB B) + reduction (round-10 layout)
static constexpr int STAGE_A = 32768;
static constexpr int STAGE_B = 16384;
static constexpr int STAGE   = STAGE_A + STAGE_B;        // 49152
static constexpr int SM_RED  = 3 * STAGE;                // 147456
static constexpr int SMEM_BYTES = SM_RED + 256 * 4 * 4;  // 151552

__device__ float g_z0[B * A];
__device__ float g_zpart[8][B * A];
__device__ float g_p[R];
__device__ float g_ctx[SCH * B * E];
__device__ __align__(16) __half g_encH[(size_t)R * E];    // 128 MB scratch
__device__ __align__(16) __half g_WencTH[(size_t)A * E];  // [a][e] fp16

__device__ __forceinline__ uint32_t smem_u32(const void* p) {
    uint32_t a;
    asm("{ .reg .u64 t; cvta.to.shared.u64 t, %1; cvt.u32.u64 %0, t; }"
        : "=r"(a) : "l"(p));
    return a;
}

#define CP16(dst, src) \
    asm volatile("cp.async.cg.shared.global [%0], [%1], 16;" \
                 :: "r"(dst), "l"(src))
#define CP_COMMIT() asm volatile("cp.async.commit_group;" ::: "memory")
#define CP_WAIT1()  asm volatile("cp.async.wait_group 1;" ::: "memory")

#define LDMX4(r0, r1, r2, r3, addr) \
    asm volatile("ldmatrix.sync.aligned.m8n8.x4.shared.b16 {%0,%1,%2,%3}, [%4];" \
                 : "=r"(r0), "=r"(r1), "=r"(r2), "=r"(r3) : "r"(addr))

__device__ __forceinline__ float fast_tanh(float x) {
    float r;
    asm("tanh.approx.f32 %0, %1;" : "=f"(r) : "f"(x));
    return r;
}

// ---------------- Kernel 0a: enc -> fp16 ----------------
__global__ void k_prep_enc(const float* __restrict__ enc) {
    const size_t i = ((size_t)blockIdx.x * 256 + threadIdx.x) * 8;
    const float4 f0 = *(const float4*)(enc + i);
    const float4 f1 = *(const float4*)(enc + i + 4);
    __half2 h[4];
    h[0] = __floats2half2_rn(f0.x, f0.y);
    h[1] = __floats2half2_rn(f0.z, f0.w);
    h[2] = __floats2half2_rn(f1.x, f1.y);
    h[3] = __floats2half2_rn(f1.z, f1.w);
    *(uint4*)&g_encH[i] = *(uint4*)h;
}

// ---------------- Kernel 0b: WencTH[a][e] = (half)Wenc[e][a] ----------------
__global__ void k_prep_wt(const float* __restrict__ Wenc) {
    __shared__ float t[32][33];
    const int bx = blockIdx.x * 32;   // a
    const int by = blockIdx.y * 32;   // e
    const int x = threadIdx.x, y = threadIdx.y;
#pragma unroll
    for (int i = 0; i < 32; i += 8)
        t[y + i][x] = Wenc[(size_t)(by + y + i) * A + bx + x];
    __syncthreads();
#pragma unroll
    for (int i = 0; i < 32; i += 8)
        g_WencTH[(size_t)(bx + y + i) * E + by + x] = __float2half_rn(t[x][y + i]);
}

// ---------------- Kernel 1a: z0 partials (K-split x8) ----------------
__global__ void k_decproj1(const float* __restrict__ dec,
                           const float* __restrict__ Wdec) {
    __shared__ float sd[128];
    const int b = blockIdx.x, ks = blockIdx.y;
    const int tid = threadIdx.x;
    if (tid < 128) sd[tid] = dec[b * D + ks * 128 + tid];
    __syncthreads();
    float a0 = 0.f, a1 = 0.f, a2 = 0.f, a3 = 0.f;
#pragma unroll 4
    for (int e = 0; e < 128; e++) {
        const float dv = sd[e];
        const float* w = Wdec + (size_t)(ks * 128 + e) * A + tid;
        a0 += dv * w[0];   a1 += dv * w[256];
        a2 += dv * w[512]; a3 += dv * w[768];
    }
    float* zp = g_zpart[ks] + b * A + tid;
    zp[0] = a0; zp[256] = a1; zp[512] = a2; zp[768] = a3;
}

// ---------------- Kernel 1b: z0 = sum partials + bias ----------------
__global__ void k_decproj2(const float* __restrict__ bias) {
    const int i = blockIdx.x * 256 + threadIdx.x;
    float s = bias[i & (A - 1)];
#pragma unroll
    for (int ks = 0; ks < 8; ks++) s += g_zpart[ks][i];
    g_z0[i] = s;
}

// ---------------- k_energy loader (512 threads, MT-parameterized) --------
template <int MT>   // MT = m-tiles per warp; BM = MT*64
__device__ __forceinline__ void issue_stage(int g, int r0, int tid,
                                            uint32_t sb) {
    const int np = g >> 4, ch = g & 15;
    const int stg = (g % 3) * STAGE;
    // A: (MT*64) rows x 128B
    if (MT == 4) {
        const int row = tid >> 1, cb = (tid & 1) * 4;
        const __half* srcA = g_encH + (size_t)(r0 + row) * E + ch * BKC + cb * 8;
        const uint32_t dA = sb + stg + row * 128;
        const int r7 = row & 7;
#pragma unroll
        for (int j = 0; j < 4; j++)
            CP16(dA + (((cb + j) ^ r7) * 16), srcA + j * 8);
    } else {
        const int row = tid >> 2, cb = (tid & 3) * 2;
        const __half* srcA = g_encH + (size_t)(r0 + row) * E + ch * BKC + cb * 8;
        const uint32_t dA = sb + stg + row * 128;
        const int r7 = row & 7;
#pragma unroll
        for (int j = 0; j < 2; j++)
            CP16(dA + (((cb + j) ^ r7) * 16), srcA + j * 8);
    }
    // B: 128 rows x 128B
    {
        const int row = tid >> 2, cb = (tid & 3) * 2;
        const __half* srcB = g_WencTH + (size_t)(np * BN + row) * E + ch * BKC + cb * 8;
        const uint32_t dB = sb + stg + STAGE_A + row * 128;
        const int r7 = row & 7;
#pragma unroll
        for (int j = 0; j < 2; j++)
            CP16(dB + (((cb + j) ^ r7) * 16), srcB + j * 8);
    }
}

template <int MT>
__device__ __forceinline__ void energy_impl(int r0, uint32_t sb, float* sred,
                                            const float* __restrict__ v,
                                            const float* __restrict__ noise) {
    const int tid = threadIdx.x;
    const int lane = tid & 31, w = tid >> 5;
    const int wm = w >> 2, wn = w & 3;        // 4 x 4 warp grid
    const int qr = lane >> 2, qc = lane & 3;

    // ldmatrix lane geometry (validated rounds 7-11)
    const int t8 = lane >> 3, rr = lane & 7;
    const int ctA = t8 >> 1;
    const int ctB = t8 & 1;
    int mrowA[MT], nrowB[2];
#pragma unroll
    for (int mt = 0; mt < MT; mt++)
        mrowA[mt] = wm * (MT * 16) + mt * 16 + (t8 & 1) * 8 + rr;
#pragma unroll
    for (int np = 0; np < 2; np++)
        nrowB[np] = wn * 32 + np * 16 + (t8 >> 1) * 8 + rr;

    float ereg[2 * MT];
#pragma unroll
    for (int q = 0; q < 2 * MT; q++) ereg[q] = 0.f;
    float c[MT][4][4];
#pragma unroll
    for (int mt = 0; mt < MT; mt++)
#pragma unroll
        for (int nt = 0; nt < 4; nt++)
#pragma unroll
            for (int q = 0; q < 4; q++) c[mt][nt][q] = 0.f;

    issue_stage<MT>(0, r0, tid, sb); CP_COMMIT();
    issue_stage<MT>(1, r0, tid, sb); CP_COMMIT();

#pragma unroll 1
    for (int g = 0; g < GTOT; g++) {
        CP_WAIT1();
        __syncthreads();

        const uint32_t aB = sb + (g % 3) * STAGE;
        const uint32_t bB = aB + STAGE_A;
#pragma unroll
        for (int ks = 0; ks < 4; ks++) {
            uint32_t af[MT][4], bf[4][2];
#pragma unroll
            for (int mt = 0; mt < MT; mt++) {
                const int cc = ks * 2 + ctA;
                const uint32_t addr =
                    aB + mrowA[mt] * 128 + ((cc ^ (mrowA[mt] & 7)) * 16);
                LDMX4(af[mt][0], af[mt][1], af[mt][2], af[mt][3], addr);
            }
#pragma unroll
            for (int ntp = 0; ntp < 2; ntp++) {
                const int cc = ks * 2 + ctB;
                const uint32_t addr =
                    bB + nrowB[ntp] * 128 + ((cc ^ (nrowB[ntp] & 7)) * 16);
                LDMX4(bf[2 * ntp][0], bf[2 * ntp][1],
                      bf[2 * ntp + 1][0], bf[2 * ntp + 1][1], addr);
            }
#pragma unroll
            for (int mt = 0; mt < MT; mt++)
#pragma unroll
                for (int nt = 0; nt < 4; nt++) {
                    asm volatile(
                        "mma.sync.aligned.m16n8k16.row.col.f32.f16.f16.f32 "
                        "{%0,%1,%2,%3}, {%4,%5,%6,%7}, {%8,%9}, {%0,%1,%2,%3};"
                        : "+f"(c[mt][nt][0]), "+f"(c[mt][nt][1]),
                          "+f"(c[mt][nt][2]), "+f"(c[mt][nt][3])
                        : "r"(af[mt][0]), "r"(af[mt][1]),
                          "r"(af[mt][2]), "r"(af[mt][3]),
                          "r"(bf[nt][0]), "r"(bf[nt][1]));
                }
        }

        if (g + 2 < GTOT) issue_stage<MT>(g + 2, r0, tid, sb);
        CP_COMMIT();   // keep group counting uniform

        if ((g & 15) == 15) {
            // epilogue for pass np = g>>4: +z0, tanh, dot v (z0/v via L1/L2)
            const int n0 = (g >> 4) * BN;
#pragma unroll
            for (int mt = 0; mt < MT; mt++)
#pragma unroll
                for (int half = 0; half < 2; half++) {
                    const int bz = (mt * 16 + half * 8 + qr) & 31;
                    const float* zr = g_z0 + bz * A + n0;
                    float acc = 0.f;
#pragma unroll
                    for (int nt = 0; nt < 4; nt++) {
                        const int lc = wn * 32 + nt * 8 + 2 * qc;
                        const float x0 = c[mt][nt][half * 2 + 0] + __ldg(zr + lc);
                        const float x1 = c[mt][nt][half * 2 + 1] + __ldg(zr + lc + 1);
                        acc = fmaf(__ldg(&v[n0 + lc]),     fast_tanh(x0), acc);
                        acc = fmaf(__ldg(&v[n0 + lc + 1]), fast_tanh(x1), acc);
                    }
                    ereg[mt * 2 + half] += acc;
#pragma unroll
                    for (int nt = 0; nt < 4; nt++) {
                        c[mt][nt][half * 2 + 0] = 0.f;
                        c[mt][nt][half * 2 + 1] = 0.f;
                    }
                }
        }
    }

    // quad reduce across qc (lanes sharing a row differ in qc only)
#pragma unroll
    for (int q = 0; q < 2 * MT; q++) {
        ereg[q] += __shfl_xor_sync(0xFFFFFFFFu, ereg[q], 1);
        ereg[q] += __shfl_xor_sync(0xFFFFFFFFu, ereg[q], 2);
    }
    __syncthreads();
    if (qc == 0) {
#pragma unroll
        for (int mt = 0; mt < MT; mt++)
#pragma unroll
            for (int half = 0; half < 2; half++) {
                const int row = wm * (MT * 16) + mt * 16 + half * 8 + qr;
                sred[row * 4 + wn] = ereg[mt * 2 + half];
            }
    }
    __syncthreads();
    if (tid < MT * 64) {
        const float e = sred[tid * 4] + sred[tid * 4 + 1] +
                        sred[tid * 4 + 2] + sred[tid * 4 + 3];
        const float x = e + noise[r0 + tid];
        g_p[r0 + tid] = 1.f / (1.f + expf(-x));
    }
}

// ---------------- Kernel 2: fp16 mma energy -> p (mixed tiling) ----------
__global__ __launch_bounds__(NTHR)
void k_energy(const float* __restrict__ v, const float* __restrict__ noise) {
    extern __shared__ __align__(1024) char smem[];
    const uint32_t sb = smem_u32(smem);
    float* sred = (float*)(smem + SM_RED);
    const int bid = blockIdx.x;
    if (bid < NBIG)
        energy_impl<4>(bid * 256, sb, sred, v, noise);
    else
        energy_impl<2>(BIGROWS + (bid - NBIG) * 128, sb, sred, v, noise);
}

// ---------------- Kernel 3: parallel monotonic scan ----------------
__global__ void k_scan(float* __restrict__ alpha) {
    __shared__ float segprod[32][33];
    __shared__ float segsum[32][33];
    const int tid = threadIdx.x;
    const int b = tid & 31, seg = tid >> 5;
    const int SL = S / 32;
    const int s0 = seg * SL;

    float prod = 1.f;
    for (int i0 = 0; i0 < SL; i0 += 8) {
        float t[8];
#pragma unroll
        for (int i = 0; i < 8; i++) t[i] = g_p[(s0 + i0 + i) * B + b];
#pragma unroll
        for (int i = 0; i < 8; i++) prod *= (1.f - t[i]);
    }
    segprod[seg][b] = prod;
    __syncthreads();

    float cp = 1.f;
    for (int s = 0; s < seg; s++) cp *= segprod[s][b];

    float run = 0.f;
    for (int i0 = 0; i0 < SL; i0 += 8) {
        float t[8];
#pragma unroll
        for (int i = 0; i < 8; i++) t[i] = g_p[(s0 + i0 + i) * B + b];
#pragma unroll
        for (int i = 0; i < 8; i++) {
            const int s = s0 + i0 + i;
            const float al = t[i] * cp;
            cp *= (1.f - t[i]);
            alpha[s * B + b] = al;
            if (s < S - 1) run += al;
        }
    }
    segsum[seg][b] = run;
    __syncthreads();

    if (tid < 32) {
        float tot = 0.f;
#pragma unroll
        for (int s = 0; s < 32; s++) tot += segsum[s][tid];
        tot = fminf(fmaxf(tot, 0.f), 1.f);
        alpha[(S - 1) * B + tid] = 1.f - tot;
    }
}

// ---------------- Kernel 4: context partials (fp16 enc) ----------------
__global__ void k_ctx(const float* __restrict__ alpha) {
    const int sc = blockIdx.x;
    const int b = blockIdx.y;
    const int tid = threadIdx.x;           // 128 threads, 8 elems each
    const int s0 = sc * (S / SCH);
    float acc[8];
#pragma unroll
    for (int k = 0; k < 8; k++) acc[k] = 0.f;
#pragma unroll 4
    for (int s = s0; s < s0 + S / SCH; s++) {
        const float al = __ldg(&alpha[s * B + b]);
        const uint4 u = *(const uint4*)&g_encH[(size_t)(s * B + b) * E + tid * 8];
        const __half2* hp = (const __half2*)&u;
#pragma unroll
        for (int k = 0; k < 4; k++) {
            const float2 f = __half22float2(hp[k]);
            acc[2 * k + 0] = fmaf(al, f.x, acc[2 * k + 0]);
            acc[2 * k + 1] = fmaf(al, f.y, acc[2 * k + 1]);
        }
    }
    float* dst = g_ctx + ((size_t)(sc * B + b)) * E + tid * 8;
    *(float4*)dst       = make_float4(acc[0], acc[1], acc[2], acc[3]);
    *(float4*)(dst + 4) = make_float4(acc[4], acc[5], acc[6], acc[7]);
}

// ---------------- Kernel 5: reduce context partials ----------------
__global__ void k_ctxred(float* __restrict__ out) {
    const int i = blockIdx.x * 256 + threadIdx.x;
    if (i >= B * E) return;
    float s = 0.f;
#pragma unroll
    for (int c = 0; c < SCH; c++) s += g_ctx[(size_t)c * B * E + i];
    out[i] = s;
}

// ---------------------------------------------------------------------------
extern "C" void kernel_launch(void* const* d_in, const int* in_sizes, int n_in,
                              void* d_out, int out_size) {
    const float* dec   = (const float*)d_in[0];
    const float* enc   = (const float*)d_in[1];
    const float* noise = (const float*)d_in[2];
    const float* Wdec  = (const float*)d_in[3];
    const float* Wenc  = (const float*)d_in[4];
    const float* bias  = (const float*)d_in[5];
    const float* v     = (const float*)d_in[6];

    float* out       = (float*)d_out;             // [B*E] weighted_context
    float* alpha_out = out + B * E;               // [S*B] alpha

    cudaFuncSetAttribute(k_energy, cudaFuncAttributeMaxDynamicSharedMemorySize,
                         SMEM_BYTES);

    k_prep_enc<<<(int)(((size_t)R * E) / 2048), 256>>>(enc);
    k_prep_wt<<<dim3(A / 32, E / 32), dim3(32, 8)>>>(Wenc);
    k_decproj1<<<dim3(B, 8), 256>>>(dec, Wdec);
    k_decproj2<<<(B * A) / 256, 256>>>(bias);

    k_energy<<<GRID_E, NTHR, SMEM_BYTES>>>(v, noise);

    k_scan<<<1, 1024>>>(alpha_out);

    dim3 gc(SCH, B);
    k_ctx<<<gc, 128>>>(alpha_out);

    k_ctxred<<<(B * E) / 256, 256>>>(out);
}

// round 14
// speedup vs baseline: 1.0626x; 1.0626x over previous
#include <cuda_runtime.h>
#include <cuda_fp16.h>
#include <cstdint>
#include <math.h>

static constexpr int S = 2048;
static constexpr int B = 32;
static constexpr int E = 1024;
static constexpr int A = 1024;
static constexpr int D = 1024;
static constexpr int R = S * B;

static constexpr int BM = 256, BN = 128;
static constexpr int BKC = 64;              // k per chunk
static constexpr int CHUNKS = E / BKC;      // 16
static constexpr int NPASS = A / BN;        // 8
static constexpr int GTOT = NPASS * CHUNKS; // 128 global chunks
static constexpr int SCH = 16;
static constexpr int NTHR = 512;

// smem: 3 stages x (32KB A + 16KB B) + reduction
static constexpr int STAGE_A = 32768;
static constexpr int STAGE_B = 16384;
static constexpr int STAGE   = STAGE_A + STAGE_B;        // 49152
static constexpr int SM_RED  = 3 * STAGE;                // 147456
static constexpr int SMEM_BYTES = SM_RED + 256 * 4 * 4;  // 151552

__device__ float g_z0[B * A];
__device__ float g_zpart[8][B * A];
__device__ float g_p[R];
__device__ float g_ctx[SCH * B * E];
__device__ __align__(16) __half g_encH[(size_t)R * E];    // 128 MB scratch
__device__ __align__(16) __half g_WencTH[(size_t)A * E];  // [a][e] fp16

__device__ __forceinline__ uint32_t smem_u32(const void* p) {
    uint32_t a;
    asm("{ .reg .u64 t; cvta.to.shared.u64 t, %1; cvt.u32.u64 %0, t; }"
        : "=r"(a) : "l"(p));
    return a;
}

#define CP16(dst, src) \
    asm volatile("cp.async.cg.shared.global [%0], [%1], 16;" \
                 :: "r"(dst), "l"(src))
#define CP_COMMIT() asm volatile("cp.async.commit_group;" ::: "memory")
#define CP_WAIT1()  asm volatile("cp.async.wait_group 1;" ::: "memory")

#define LDMX4(r0, r1, r2, r3, addr) \
    asm volatile("ldmatrix.sync.aligned.m8n8.x4.shared.b16 {%0,%1,%2,%3}, [%4];" \
                 : "=r"(r0), "=r"(r1), "=r"(r2), "=r"(r3) : "r"(addr))

__device__ __forceinline__ float fast_tanh(float x) {
    float r;
    asm("tanh.approx.f32 %0, %1;" : "=f"(r) : "f"(x));
    return r;
}

// ---------------- Kernel 0a: enc -> fp16 ----------------
__global__ void k_prep_enc(const float* __restrict__ enc) {
    const size_t i = ((size_t)blockIdx.x * 256 + threadIdx.x) * 8;
    const float4 f0 = *(const float4*)(enc + i);
    const float4 f1 = *(const float4*)(enc + i + 4);
    __half2 h[4];
    h[0] = __floats2half2_rn(f0.x, f0.y);
    h[1] = __floats2half2_rn(f0.z, f0.w);
    h[2] = __floats2half2_rn(f1.x, f1.y);
    h[3] = __floats2half2_rn(f1.z, f1.w);
    *(uint4*)&g_encH[i] = *(uint4*)h;
}

// ---------------- Kernel 0b: WencTH[a][e] = (half)Wenc[e][a] ----------------
__global__ void k_prep_wt(const float* __restrict__ Wenc) {
    __shared__ float t[32][33];
    const int bx = blockIdx.x * 32;   // a
    const int by = blockIdx.y * 32;   // e
    const int x = threadIdx.x, y = threadIdx.y;
#pragma unroll
    for (int i = 0; i < 32; i += 8)
        t[y + i][x] = Wenc[(size_t)(by + y + i) * A + bx + x];
    __syncthreads();
#pragma unroll
    for (int i = 0; i < 32; i += 8)
        g_WencTH[(size_t)(bx + y + i) * E + by + x] = __float2half_rn(t[x][y + i]);
}

// ---------------- Kernel 1a: z0 partials (K-split x8) ----------------
__global__ void k_decproj1(const float* __restrict__ dec,
                           const float* __restrict__ Wdec) {
    __shared__ float sd[128];
    const int b = blockIdx.x, ks = blockIdx.y;
    const int tid = threadIdx.x;
    if (tid < 128) sd[tid] = dec[b * D + ks * 128 + tid];
    __syncthreads();
    float a0 = 0.f, a1 = 0.f, a2 = 0.f, a3 = 0.f;
#pragma unroll 4
    for (int e = 0; e < 128; e++) {
        const float dv = sd[e];
        const float* w = Wdec + (size_t)(ks * 128 + e) * A + tid;
        a0 += dv * w[0];   a1 += dv * w[256];
        a2 += dv * w[512]; a3 += dv * w[768];
    }
    float* zp = g_zpart[ks] + b * A + tid;
    zp[0] = a0; zp[256] = a1; zp[512] = a2; zp[768] = a3;
}

// ---------------- Kernel 1b: z0 = sum partials + bias ----------------
__global__ void k_decproj2(const float* __restrict__ bias) {
    const int i = blockIdx.x * 256 + threadIdx.x;
    float s = bias[i & (A - 1)];
#pragma unroll
    for (int ks = 0; ks < 8; ks++) s += g_zpart[ks][i];
    g_z0[i] = s;
}

// ---------------- k_energy loader (512 threads) ----------------
__device__ __forceinline__ void issue_stage(int g, int r0, int tid,
                                            uint32_t sb) {
    const int np = g >> 4, ch = g & 15;
    const int stg = (g % 3) * STAGE;
    // A: 256 rows x 128B, 4 x 16B per thread
    {
        const int row = tid >> 1, cb = (tid & 1) * 4;
        const __half* srcA = g_encH + (size_t)(r0 + row) * E + ch * BKC + cb * 8;
        const uint32_t dA = sb + stg + row * 128;
        const int r7 = row & 7;
#pragma unroll
        for (int j = 0; j < 4; j++)
            CP16(dA + (((cb + j) ^ r7) * 16), srcA + j * 8);
    }
    // B: 128 rows x 128B, 2 x 16B per thread
    {
        const int row = tid >> 2, cb = (tid & 3) * 2;
        const __half* srcB = g_WencTH + (size_t)(np * BN + row) * E + ch * BKC + cb * 8;
        const uint32_t dB = sb + stg + STAGE_A + row * 128;
        const int r7 = row & 7;
#pragma unroll
        for (int j = 0; j < 2; j++)
            CP16(dB + (((cb + j) ^ r7) * 16), srcB + j * 8);
    }
}

// ---------------- Kernel 2: fp16 mma energy -> p ----------------
__global__ __launch_bounds__(NTHR)
void k_energy(const float* __restrict__ v, const float* __restrict__ noise) {
    extern __shared__ __align__(1024) char smem[];
    const uint32_t sb = smem_u32(smem);
    float* sred = (float*)(smem + SM_RED);

    const int tid = threadIdx.x;
    const int lane = tid & 31, w = tid >> 5;
    const int wm = w >> 2, wn = w & 3;        // 4 x 4 warp grid, tile 64x32
    const int qr = lane >> 2, qc = lane & 3;
    const int r0 = blockIdx.x * BM;

    // ldmatrix lane geometry (validated rounds 7-12)
    const int t8 = lane >> 3, rr = lane & 7;
    const int ctA = t8 >> 1;
    const int ctB = t8 & 1;
    int mrowA[4], nrowB[2];
#pragma unroll
    for (int mt = 0; mt < 4; mt++) mrowA[mt] = wm * 64 + mt * 16 + (t8 & 1) * 8 + rr;
#pragma unroll
    for (int np = 0; np < 2; np++) nrowB[np] = wn * 32 + np * 16 + (t8 >> 1) * 8 + rr;

    float ereg[8];
#pragma unroll
    for (int q = 0; q < 8; q++) ereg[q] = 0.f;
    float c[4][4][4];
#pragma unroll
    for (int mt = 0; mt < 4; mt++)
#pragma unroll
        for (int nt = 0; nt < 4; nt++)
#pragma unroll
            for (int q = 0; q < 4; q++) c[mt][nt][q] = 0.f;

    issue_stage(0, r0, tid, sb); CP_COMMIT();
    issue_stage(1, r0, tid, sb); CP_COMMIT();

#pragma unroll 1
    for (int g = 0; g < GTOT; g++) {
        CP_WAIT1();
        __syncthreads();

        const uint32_t aB = sb + (g % 3) * STAGE;
        const uint32_t bB = aB + STAGE_A;
#pragma unroll
        for (int ks = 0; ks < 4; ks++) {
            uint32_t af[4][4], bf[4][2];
#pragma unroll
            for (int mt = 0; mt < 4; mt++) {
                const int cc = ks * 2 + ctA;
                const uint32_t addr =
                    aB + mrowA[mt] * 128 + ((cc ^ (mrowA[mt] & 7)) * 16);
                LDMX4(af[mt][0], af[mt][1], af[mt][2], af[mt][3], addr);
            }
#pragma unroll
            for (int ntp = 0; ntp < 2; ntp++) {
                const int cc = ks * 2 + ctB;
                const uint32_t addr =
                    bB + nrowB[ntp] * 128 + ((cc ^ (nrowB[ntp] & 7)) * 16);
                LDMX4(bf[2 * ntp][0], bf[2 * ntp][1],
                      bf[2 * ntp + 1][0], bf[2 * ntp + 1][1], addr);
            }
#pragma unroll
            for (int mt = 0; mt < 4; mt++)
#pragma unroll
                for (int nt = 0; nt < 4; nt++) {
                    asm volatile(
                        "mma.sync.aligned.m16n8k16.row.col.f32.f16.f16.f32 "
                        "{%0,%1,%2,%3}, {%4,%5,%6,%7}, {%8,%9}, {%0,%1,%2,%3};"
                        : "+f"(c[mt][nt][0]), "+f"(c[mt][nt][1]),
                          "+f"(c[mt][nt][2]), "+f"(c[mt][nt][3])
                        : "r"(af[mt][0]), "r"(af[mt][1]),
                          "r"(af[mt][2]), "r"(af[mt][3]),
                          "r"(bf[nt][0]), "r"(bf[nt][1]));
                }
        }

        if (g + 2 < GTOT) issue_stage(g + 2, r0, tid, sb);
        CP_COMMIT();   // keep group counting uniform

        if ((g & 15) == 15) {
            // epilogue for pass np = g>>4: +z0, tanh, dot v (z0/v via L1/L2)
            const int n0 = (g >> 4) * BN;
#pragma unroll
            for (int mt = 0; mt < 4; mt++)
#pragma unroll
                for (int half = 0; half < 2; half++) {
                    const int bz = (mt * 16 + half * 8 + qr) & 31;
                    const float* zr = g_z0 + bz * A + n0;
                    float acc = 0.f;
#pragma unroll
                    for (int nt = 0; nt < 4; nt++) {
                        const int lc = wn * 32 + nt * 8 + 2 * qc;
                        const float x0 = c[mt][nt][half * 2 + 0] + __ldg(zr + lc);
                        const float x1 = c[mt][nt][half * 2 + 1] + __ldg(zr + lc + 1);
                        acc = fmaf(__ldg(&v[n0 + lc]),     fast_tanh(x0), acc);
                        acc = fmaf(__ldg(&v[n0 + lc + 1]), fast_tanh(x1), acc);
                    }
                    ereg[mt * 2 + half] += acc;
#pragma unroll
                    for (int nt = 0; nt < 4; nt++) {
                        c[mt][nt][half * 2 + 0] = 0.f;
                        c[mt][nt][half * 2 + 1] = 0.f;
                    }
                }
        }
    }

    // quad reduce across qc (lanes sharing a row differ in qc only)
#pragma unroll
    for (int q = 0; q < 8; q++) {
        ereg[q] += __shfl_xor_sync(0xFFFFFFFFu, ereg[q], 1);
        ereg[q] += __shfl_xor_sync(0xFFFFFFFFu, ereg[q], 2);
    }
    __syncthreads();
    if (qc == 0) {
#pragma unroll
        for (int mt = 0; mt < 4; mt++)
#pragma unroll
            for (int half = 0; half < 2; half++) {
                const int row = wm * 64 + mt * 16 + half * 8 + qr;
                sred[row * 4 + wn] = ereg[mt * 2 + half];
            }
    }
    __syncthreads();
    if (tid < BM) {
        const float e = sred[tid * 4] + sred[tid * 4 + 1] +
                        sred[tid * 4 + 2] + sred[tid * 4 + 3];
        const float x = e + noise[r0 + tid];
        g_p[r0 + tid] = 1.f / (1.f + expf(-x));
    }
}

// ---------------- Kernel 3: parallel monotonic scan ----------------
__global__ void k_scan(float* __restrict__ alpha) {
    __shared__ float segprod[32][33];
    __shared__ float segsum[32][33];
    const int tid = threadIdx.x;
    const int b = tid & 31, seg = tid >> 5;
    const int SL = S / 32;
    const int s0 = seg * SL;

    float prod = 1.f;
    for (int i0 = 0; i0 < SL; i0 += 8) {
        float t[8];
#pragma unroll
        for (int i = 0; i < 8; i++) t[i] = g_p[(s0 + i0 + i) * B + b];
#pragma unroll
        for (int i = 0; i < 8; i++) prod *= (1.f - t[i]);
    }
    segprod[seg][b] = prod;
    __syncthreads();

    float cp = 1.f;
    for (int s = 0; s < seg; s++) cp *= segprod[s][b];

    float run = 0.f;
    for (int i0 = 0; i0 < SL; i0 += 8) {
        float t[8];
#pragma unroll
        for (int i = 0; i < 8; i++) t[i] = g_p[(s0 + i0 + i) * B + b];
#pragma unroll
        for (int i = 0; i < 8; i++) {
            const int s = s0 + i0 + i;
            const float al = t[i] * cp;
            cp *= (1.f - t[i]);
            alpha[s * B + b] = al;
            if (s < S - 1) run += al;
        }
    }
    segsum[seg][b] = run;
    __syncthreads();

    if (tid < 32) {
        float tot = 0.f;
#pragma unroll
        for (int s = 0; s < 32; s++) tot += segsum[s][tid];
        tot = fminf(fmaxf(tot, 0.f), 1.f);
        alpha[(S - 1) * B + tid] = 1.f - tot;
    }
}

// ---------------- Kernel 4: context partials (fp16 enc) ----------------
__global__ void k_ctx(const float* __restrict__ alpha) {
    const int sc = blockIdx.x;
    const int b = blockIdx.y;
    const int tid = threadIdx.x;           // 128 threads, 8 elems each
    const int s0 = sc * (S / SCH);
    float acc[8];
#pragma unroll
    for (int k = 0; k < 8; k++) acc[k] = 0.f;
#pragma unroll 4
    for (int s = s0; s < s0 + S / SCH; s++) {
        const float al = __ldg(&alpha[s * B + b]);
        const uint4 u = *(const uint4*)&g_encH[(size_t)(s * B + b) * E + tid * 8];
        const __half2* hp = (const __half2*)&u;
#pragma unroll
        for (int k = 0; k < 4; k++) {
            const float2 f = __half22float2(hp[k]);
            acc[2 * k + 0] = fmaf(al, f.x, acc[2 * k + 0]);
            acc[2 * k + 1] = fmaf(al, f.y, acc[2 * k + 1]);
        }
    }
    float* dst = g_ctx + ((size_t)(sc * B + b)) * E + tid * 8;
    *(float4*)dst       = make_float4(acc[0], acc[1], acc[2], acc[3]);
    *(float4*)(dst + 4) = make_float4(acc[4], acc[5], acc[6], acc[7]);
}

// ---------------- Kernel 5: reduce context partials ----------------
__global__ void k_ctxred(float* __restrict__ out) {
    const int i = blockIdx.x * 256 + threadIdx.x;
    if (i >= B * E) return;
    float s = 0.f;
#pragma unroll
    for (int c = 0; c < SCH; c++) s += g_ctx[(size_t)c * B * E + i];
    out[i] = s;
}

// ---------------------------------------------------------------------------
extern "C" void kernel_launch(void* const* d_in, const int* in_sizes, int n_in,
                              void* d_out, int out_size) {
    const float* dec   = (const float*)d_in[0];
    const float* enc   = (const float*)d_in[1];
    const float* noise = (const float*)d_in[2];
    const float* Wdec  = (const float*)d_in[3];
    const float* Wenc  = (const float*)d_in[4];
    const float* bias  = (const float*)d_in[5];
    const float* v     = (const float*)d_in[6];

    float* out       = (float*)d_out;             // [B*E] weighted_context
    float* alpha_out = out + B * E;               // [S*B] alpha

    cudaFuncSetAttribute(k_energy, cudaFuncAttributeMaxDynamicSharedMemorySize,
                         SMEM_BYTES);

    k_prep_enc<<<(int)(((size_t)R * E) / 2048), 256>>>(enc);
    k_prep_wt<<<dim3(A / 32, E / 32), dim3(32, 8)>>>(Wenc);
    k_decproj1<<<dim3(B, 8), 256>>>(dec, Wdec);
    k_decproj2<<<(B * A) / 256, 256>>>(bias);

    k_energy<<<R / BM, NTHR, SMEM_BYTES>>>(v, noise);

    k_scan<<<1, 1024>>>(alpha_out);

    dim3 gc(SCH, B);
    k_ctx<<<gc, 128>>>(alpha_out);

    k_ctxred<<<(B * E) / 256, 256>>>(out);
}

// round 15
// speedup vs baseline: 1.1861x; 1.1163x over previous
#include <cuda_runtime.h>
#include <cuda_fp16.h>
#include <cstdint>
#include <math.h>

static constexpr int S = 2048;
static constexpr int B = 32;
static constexpr int E = 1024;
static constexpr int A = 1024;
static constexpr int D = 1024;
static constexpr int R = S * B;

static constexpr int BM = 256, BN = 128;
static constexpr int BKC = 64;              // k per chunk
static constexpr int CHUNKS = E / BKC;      // 16
static constexpr int NPASS = A / BN;        // 8
static constexpr int SCH = 16;
static constexpr int NTHR = 512;

// persistent scheduling: 2048 units = 256 tiles x 8 passes over 148 CTAs
static constexpr int GRID_E = 148;
static constexpr int NUNITS = (R / BM) * NPASS;   // 2048
static constexpr int UPC  = NUNITS / GRID_E;      // 13
static constexpr int UREM = NUNITS % GRID_E;      // 124 CTAs get 14

// smem: 3 stages x (32KB A + 16KB B) + reduction
static constexpr int STAGE_A = 32768;
static constexpr int STAGE_B = 16384;
static constexpr int STAGE   = STAGE_A + STAGE_B;        // 49152
static constexpr int SM_RED  = 3 * STAGE;                // 147456
static constexpr int SMEM_BYTES = SM_RED + 256 * 4 * 4;  // 151552

__device__ float g_z0[B * A];
__device__ float g_zpart[8][B * A];
__device__ float g_eu[NPASS * R];                         // per-pass energy partials (2 MB)
__device__ float g_p[R];
__device__ float g_ctx[SCH * B * E];
__device__ __align__(16) __half g_encH[(size_t)R * E];    // 128 MB scratch
__device__ __align__(16) __half g_WencTH[(size_t)A * E];  // [a][e] fp16

__device__ __forceinline__ uint32_t smem_u32(const void* p) {
    uint32_t a;
    asm("{ .reg .u64 t; cvta.to.shared.u64 t, %1; cvt.u32.u64 %0, t; }"
        : "=r"(a) : "l"(p));
    return a;
}

#define CP16(dst, src) \
    asm volatile("cp.async.cg.shared.global [%0], [%1], 16;" \
                 :: "r"(dst), "l"(src))
#define CP_COMMIT() asm volatile("cp.async.commit_group;" ::: "memory")
#define CP_WAIT1()  asm volatile("cp.async.wait_group 1;" ::: "memory")

#define LDMX4(r0, r1, r2, r3, addr) \
    asm volatile("ldmatrix.sync.aligned.m8n8.x4.shared.b16 {%0,%1,%2,%3}, [%4];" \
                 : "=r"(r0), "=r"(r1), "=r"(r2), "=r"(r3) : "r"(addr))

__device__ __forceinline__ float fast_tanh(float x) {
    float e, r;
    asm("ex2.approx.f32 %0, %1;" : "=f"(e) : "f"(x * 2.885390082f));
    asm("rcp.approx.f32 %0, %1;" : "=f"(r) : "f"(e + 1.f));
    return fmaf(-2.f, r, 1.f);
}

// ---------------- Kernel 0a: enc -> fp16 ----------------
__global__ void k_prep_enc(const float* __restrict__ enc) {
    const size_t i = ((size_t)blockIdx.x * 256 + threadIdx.x) * 8;
    const float4 f0 = *(const float4*)(enc + i);
    const float4 f1 = *(const float4*)(enc + i + 4);
    __half2 h[4];
    h[0] = __floats2half2_rn(f0.x, f0.y);
    h[1] = __floats2half2_rn(f0.z, f0.w);
    h[2] = __floats2half2_rn(f1.x, f1.y);
    h[3] = __floats2half2_rn(f1.z, f1.w);
    *(uint4*)&g_encH[i] = *(uint4*)h;
}

// ---------------- Kernel 0b: WencTH[a][e] = (half)Wenc[e][a] ----------------
__global__ void k_prep_wt(const float* __restrict__ Wenc) {
    __shared__ float t[32][33];
    const int bx = blockIdx.x * 32;   // a
    const int by = blockIdx.y * 32;   // e
    const int x = threadIdx.x, y = threadIdx.y;
#pragma unroll
    for (int i = 0; i < 32; i += 8)
        t[y + i][x] = Wenc[(size_t)(by + y + i) * A + bx + x];
    __syncthreads();
#pragma unroll
    for (int i = 0; i < 32; i += 8)
        g_WencTH[(size_t)(bx + y + i) * E + by + x] = __float2half_rn(t[x][y + i]);
}

// ---------------- Kernel 1a: z0 partials (K-split x8) ----------------
__global__ void k_decproj1(const float* __restrict__ dec,
                           const float* __restrict__ Wdec) {
    __shared__ float sd[128];
    const int b = blockIdx.x, ks = blockIdx.y;
    const int tid = threadIdx.x;
    if (tid < 128) sd[tid] = dec[b * D + ks * 128 + tid];
    __syncthreads();
    float a0 = 0.f, a1 = 0.f, a2 = 0.f, a3 = 0.f;
#pragma unroll 4
    for (int e = 0; e < 128; e++) {
        const float dv = sd[e];
        const float* w = Wdec + (size_t)(ks * 128 + e) * A + tid;
        a0 += dv * w[0];   a1 += dv * w[256];
        a2 += dv * w[512]; a3 += dv * w[768];
    }
    float* zp = g_zpart[ks] + b * A + tid;
    zp[0] = a0; zp[256] = a1; zp[512] = a2; zp[768] = a3;
}

// ---------------- Kernel 1b: z0 = sum partials + bias ----------------
__global__ void k_decproj2(const float* __restrict__ bias) {
    const int i = blockIdx.x * 256 + threadIdx.x;
    float s = bias[i & (A - 1)];
#pragma unroll
    for (int ks = 0; ks < 8; ks++) s += g_zpart[ks][i];
    g_z0[i] = s;
}

// ---------------- k_energy loader (512 threads) ----------------
// local chunk lc -> unit u = ustart + (lc>>4), ch = lc&15
__device__ __forceinline__ void issue_stage(int lc, int ustart, int tid,
                                            uint32_t sb) {
    const int u = ustart + (lc >> 4);
    const int ch = lc & 15;
    const int np = u & 7;
    const int r0 = (u >> 3) << 8;            // tile * 256
    const int stg = (lc % 3) * STAGE;
    // A: 256 rows x 128B, 4 x 16B per thread
    {
        const int row = tid >> 1, cb = (tid & 1) * 4;
        const __half* srcA = g_encH + (size_t)(r0 + row) * E + ch * BKC + cb * 8;
        const uint32_t dA = sb + stg + row * 128;
        const int r7 = row & 7;
#pragma unroll
        for (int j = 0; j < 4; j++)
            CP16(dA + (((cb + j) ^ r7) * 16), srcA + j * 8);
    }
    // B: 128 rows x 128B, 2 x 16B per thread
    {
        const int row = tid >> 2, cb = (tid & 3) * 2;
        const __half* srcB = g_WencTH + (size_t)(np * BN + row) * E + ch * BKC + cb * 8;
        const uint32_t dB = sb + stg + STAGE_A + row * 128;
        const int r7 = row & 7;
#pragma unroll
        for (int j = 0; j < 2; j++)
            CP16(dB + (((cb + j) ^ r7) * 16), srcB + j * 8);
    }
}

// ---------------- Kernel 2: fp16 mma energy -> per-pass partials ----------
__global__ __launch_bounds__(NTHR)
void k_energy(const float* __restrict__ v) {
    extern __shared__ __align__(1024) char smem[];
    const uint32_t sb = smem_u32(smem);
    float* sred = (float*)(smem + SM_RED);

    const int tid = threadIdx.x;
    const int lane = tid & 31, w = tid >> 5;
    const int wm = w >> 2, wn = w & 3;        // 4 x 4 warp grid, tile 64x32
    const int qr = lane >> 2, qc = lane & 3;

    const int bid = blockIdx.x;
    const int cnt = (bid < UREM) ? (UPC + 1) : UPC;
    const int ustart = (bid < UREM) ? bid * (UPC + 1)
                                    : UREM * (UPC + 1) + (bid - UREM) * UPC;
    const int nch = cnt * 16;

    // ldmatrix lane geometry (validated rounds 7-13)
    const int t8 = lane >> 3, rr = lane & 7;
    const int ctA = t8 >> 1;
    const int ctB = t8 & 1;
    int mrowA[4], nrowB[2];
#pragma unroll
    for (int mt = 0; mt < 4; mt++) mrowA[mt] = wm * 64 + mt * 16 + (t8 & 1) * 8 + rr;
#pragma unroll
    for (int np = 0; np < 2; np++) nrowB[np] = wn * 32 + np * 16 + (t8 >> 1) * 8 + rr;

    float c[4][4][4];
#pragma unroll
    for (int mt = 0; mt < 4; mt++)
#pragma unroll
        for (int nt = 0; nt < 4; nt++)
#pragma unroll
            for (int q = 0; q < 4; q++) c[mt][nt][q] = 0.f;

    issue_stage(0, ustart, tid, sb); CP_COMMIT();
    issue_stage(1, ustart, tid, sb); CP_COMMIT();

#pragma unroll 1
    for (int lc = 0; lc < nch; lc++) {
        CP_WAIT1();
        __syncthreads();

        const uint32_t aB = sb + (lc % 3) * STAGE;
        const uint32_t bB = aB + STAGE_A;
#pragma unroll
        for (int ks = 0; ks < 4; ks++) {
            uint32_t af[4][4], bf[4][2];
#pragma unroll
            for (int mt = 0; mt < 4; mt++) {
                const int cc = ks * 2 + ctA;
                const uint32_t addr =
                    aB + mrowA[mt] * 128 + ((cc ^ (mrowA[mt] & 7)) * 16);
                LDMX4(af[mt][0], af[mt][1], af[mt][2], af[mt][3], addr);
            }
#pragma unroll
            for (int ntp = 0; ntp < 2; ntp++) {
                const int cc = ks * 2 + ctB;
                const uint32_t addr =
                    bB + nrowB[ntp] * 128 + ((cc ^ (nrowB[ntp] & 7)) * 16);
                LDMX4(bf[2 * ntp][0], bf[2 * ntp][1],
                      bf[2 * ntp + 1][0], bf[2 * ntp + 1][1], addr);
            }
#pragma unroll
            for (int mt = 0; mt < 4; mt++)
#pragma unroll
                for (int nt = 0; nt < 4; nt++) {
                    asm volatile(
                        "mma.sync.aligned.m16n8k16.row.col.f32.f16.f16.f32 "
                        "{%0,%1,%2,%3}, {%4,%5,%6,%7}, {%8,%9}, {%0,%1,%2,%3};"
                        : "+f"(c[mt][nt][0]), "+f"(c[mt][nt][1]),
                          "+f"(c[mt][nt][2]), "+f"(c[mt][nt][3])
                        : "r"(af[mt][0]), "r"(af[mt][1]),
                          "r"(af[mt][2]), "r"(af[mt][3]),
                          "r"(bf[nt][0]), "r"(bf[nt][1]));
                }
        }

        if (lc + 2 < nch) issue_stage(lc + 2, ustart, tid, sb);
        CP_COMMIT();   // keep group counting uniform

        if ((lc & 15) == 15) {
            // unit epilogue: +z0, tanh, dot v -> per-pass partial (deterministic)
            const int u = ustart + (lc >> 4);
            const int np = u & 7;
            const int r0 = (u >> 3) << 8;
            const int n0 = np * BN;
            float er[8];
#pragma unroll
            for (int mt = 0; mt < 4; mt++)
#pragma unroll
                for (int half = 0; half < 2; half++) {
                    const int bz = (mt * 16 + half * 8 + qr) & 31;
                    const float* zr = g_z0 + bz * A + n0;
                    float acc = 0.f;
#pragma unroll
                    for (int nt = 0; nt < 4; nt++) {
                        const int lc2 = wn * 32 + nt * 8 + 2 * qc;
                        const float x0 = c[mt][nt][half * 2 + 0] + __ldg(zr + lc2);
                        const float x1 = c[mt][nt][half * 2 + 1] + __ldg(zr + lc2 + 1);
                        acc = fmaf(__ldg(&v[n0 + lc2]),     fast_tanh(x0), acc);
                        acc = fmaf(__ldg(&v[n0 + lc2 + 1]), fast_tanh(x1), acc);
                    }
                    er[mt * 2 + half] = acc;
                }
            // zero accumulators for the next unit
#pragma unroll
            for (int mt = 0; mt < 4; mt++)
#pragma unroll
                for (int nt = 0; nt < 4; nt++)
#pragma unroll
                    for (int q = 0; q < 4; q++) c[mt][nt][q] = 0.f;

            // quad reduce across qc, then cross-warp (wn) via smem
#pragma unroll
            for (int q = 0; q < 8; q++) {
                er[q] += __shfl_xor_sync(0xFFFFFFFFu, er[q], 1);
                er[q] += __shfl_xor_sync(0xFFFFFFFFu, er[q], 2);
            }
            if (qc == 0) {
#pragma unroll
                for (int mt = 0; mt < 4; mt++)
#pragma unroll
                    for (int half = 0; half < 2; half++) {
                        const int row = wm * 64 + mt * 16 + half * 8 + qr;
                        sred[row * 4 + wn] = er[mt * 2 + half];
                    }
            }
            __syncthreads();
            if (tid < BM) {
                g_eu[np * R + r0 + tid] =
                    sred[tid * 4] + sred[tid * 4 + 1] +
                    sred[tid * 4 + 2] + sred[tid * 4 + 3];
            }
            // sred safe to reuse: next write is >=16 chunks away, each with barriers
        }
    }
}

// ---------------- Kernel 2b: p = sigmoid(sum partials + noise) ----------
__global__ void k_p(const float* __restrict__ noise) {
    const int i = blockIdx.x * 256 + threadIdx.x;
    float s = noise[i];
#pragma unroll
    for (int np = 0; np < NPASS; np++) s += g_eu[np * R + i];
    g_p[i] = 1.f / (1.f + expf(-s));
}

// ---------------- Kernel 3: parallel monotonic scan ----------------
__global__ void k_scan(float* __restrict__ alpha) {
    __shared__ float segprod[32][33];
    __shared__ float segsum[32][33];
    const int tid = threadIdx.x;
    const int b = tid & 31, seg = tid >> 5;
    const int SL = S / 32;
    const int s0 = seg * SL;

    float prod = 1.f;
    for (int i0 = 0; i0 < SL; i0 += 8) {
        float t[8];
#pragma unroll
        for (int i = 0; i < 8; i++) t[i] = g_p[(s0 + i0 + i) * B + b];
#pragma unroll
        for (int i = 0; i < 8; i++) prod *= (1.f - t[i]);
    }
    segprod[seg][b] = prod;
    __syncthreads();

    float cp = 1.f;
    for (int s = 0; s < seg; s++) cp *= segprod[s][b];

    float run = 0.f;
    for (int i0 = 0; i0 < SL; i0 += 8) {
        float t[8];
#pragma unroll
        for (int i = 0; i < 8; i++) t[i] = g_p[(s0 + i0 + i) * B + b];
#pragma unroll
        for (int i = 0; i < 8; i++) {
            const int s = s0 + i0 + i;
            const float al = t[i] * cp;
            cp *= (1.f - t[i]);
            alpha[s * B + b] = al;
            if (s < S - 1) run += al;
        }
    }
    segsum[seg][b] = run;
    __syncthreads();

    if (tid < 32) {
        float tot = 0.f;
#pragma unroll
        for (int s = 0; s < 32; s++) tot += segsum[s][tid];
        tot = fminf(fmaxf(tot, 0.f), 1.f);
        alpha[(S - 1) * B + tid] = 1.f - tot;
    }
}

// ---------------- Kernel 4: context partials (fp16 enc) ----------------
__global__ void k_ctx(const float* __restrict__ alpha) {
    const int sc = blockIdx.x;
    const int b = blockIdx.y;
    const int tid = threadIdx.x;           // 128 threads, 8 elems each
    const int s0 = sc * (S / SCH);
    float acc[8];
#pragma unroll
    for (int k = 0; k < 8; k++) acc[k] = 0.f;
#pragma unroll 4
    for (int s = s0; s < s0 + S / SCH; s++) {
        const float al = __ldg(&alpha[s * B + b]);
        const uint4 u = *(const uint4*)&g_encH[(size_t)(s * B + b) * E + tid * 8];
        const __half2* hp = (const __half2*)&u;
#pragma unroll
        for (int k = 0; k < 4; k++) {
            const float2 f = __half22float2(hp[k]);
            acc[2 * k + 0] = fmaf(al, f.x, acc[2 * k + 0]);
            acc[2 * k + 1] = fmaf(al, f.y, acc[2 * k + 1]);
        }
    }
    float* dst = g_ctx + ((size_t)(sc * B + b)) * E + tid * 8;
    *(float4*)dst       = make_float4(acc[0], acc[1], acc[2], acc[3]);
    *(float4*)(dst + 4) = make_float4(acc[4], acc[5], acc[6], acc[7]);
}

// ---------------- Kernel 5: reduce context partials ----------------
__global__ void k_ctxred(float* __restrict__ out) {
    const int i = blockIdx.x * 256 + threadIdx.x;
    if (i >= B * E) return;
    float s = 0.f;
#pragma unroll
    for (int c = 0; c < SCH; c++) s += g_ctx[(size_t)c * B * E + i];
    out[i] = s;
}

// ---------------------------------------------------------------------------
extern "C" void kernel_launch(void* const* d_in, const int* in_sizes, int n_in,
                              void* d_out, int out_size) {
    const float* dec   = (const float*)d_in[0];
    const float* enc   = (const float*)d_in[1];
    const float* noise = (const float*)d_in[2];
    const float* Wdec  = (const float*)d_in[3];
    const float* Wenc  = (const float*)d_in[4];
    const float* bias  = (const float*)d_in[5];
    const float* v     = (const float*)d_in[6];

    float* out       = (float*)d_out;             // [B*E] weighted_context
    float* alpha_out = out + B * E;               // [S*B] alpha

    cudaFuncSetAttribute(k_energy, cudaFuncAttributeMaxDynamicSharedMemorySize,
                         SMEM_BYTES);

    k_prep_enc<<<(int)(((size_t)R * E) / 2048), 256>>>(enc);
    k_prep_wt<<<dim3(A / 32, E / 32), dim3(32, 8)>>>(Wenc);
    k_decproj1<<<dim3(B, 8), 256>>>(dec, Wdec);
    k_decproj2<<<(B * A) / 256, 256>>>(bias);

    k_energy<<<GRID_E, NTHR, SMEM_BYTES>>>(v);

    k_p<<<R / 256, 256>>>(noise);

    k_scan<<<1, 1024>>>(alpha_out);

    dim3 gc(SCH, B);
    k_ctx<<<gc, 128>>>(alpha_out);

    k_ctxred<<<(B * E) / 256, 256>>>(out);
}